// round 1
// baseline (speedup 1.0000x reference)
#include <cuda_runtime.h>
#include <cuda_bf16.h>
#include <math.h>

// Problem constants
#define L_SEQ   2048
#define DM      1024      // d_model
#define DI      1024      // d_inner
#define DTR     64        // dt_rank
#define DS      16        // d_state
#define PROJ    (DTR + 2 * DI * DS)   // 32832

// -------- scratch (static device globals; no allocation) --------
__device__ float g_dbc[(size_t)L_SEQ * PROJ];      // 269 MB: [L, PROJ]
__device__ float g_delta[(size_t)L_SEQ * DI];      // 8 MB
__device__ float g_y[(size_t)L_SEQ * DI];          // 8 MB

// ============================================================================
// Generic TN SGEMM: C[m,n] = sum_k A[m*lda+k] * B[n*ldb+k]
// 128x128 tile, BK=8, 256 threads, 8x8 per-thread microtile.
// Requires M % 128 == 0, K % 8 == 0. N ragged (guarded), N % 8 == 0.
// ============================================================================
__global__ __launch_bounds__(256) void sgemm_tn(
    const float* __restrict__ A, const float* __restrict__ B,
    float* __restrict__ C, int M, int N, int K, int lda, int ldb, int ldc)
{
    __shared__ float As[8][128];
    __shared__ float Bs[8][128];

    const int tid = threadIdx.x;
    const int m0 = blockIdx.y * 128;
    const int n0 = blockIdx.x * 128;

    const int lr = tid >> 1;          // 0..127: row within tile for loads
    const int lk = (tid & 1) * 4;     // 0 or 4: k offset for float4 load
    const int tx = tid & 15;          // 0..15
    const int ty = tid >> 4;          // 0..15

    float acc[8][8];
    #pragma unroll
    for (int i = 0; i < 8; i++)
        #pragma unroll
        for (int j = 0; j < 8; j++) acc[i][j] = 0.f;

    const float* Aptr = A + (size_t)(m0 + lr) * lda + lk;
    const float* Bptr = B + (size_t)(n0 + lr) * ldb + lk;
    const bool bvalid = (n0 + lr) < N;

    for (int k0 = 0; k0 < K; k0 += 8) {
        float4 av = *(const float4*)(Aptr + k0);
        float4 bv = make_float4(0.f, 0.f, 0.f, 0.f);
        if (bvalid) bv = *(const float4*)(Bptr + k0);

        As[lk + 0][lr] = av.x; As[lk + 1][lr] = av.y;
        As[lk + 2][lr] = av.z; As[lk + 3][lr] = av.w;
        Bs[lk + 0][lr] = bv.x; Bs[lk + 1][lr] = bv.y;
        Bs[lk + 2][lr] = bv.z; Bs[lk + 3][lr] = bv.w;
        __syncthreads();

        #pragma unroll
        for (int kk = 0; kk < 8; kk++) {
            float a8[8], b8[8];
            #pragma unroll
            for (int i = 0; i < 8; i++) a8[i] = As[kk][ty * 8 + i];
            #pragma unroll
            for (int j = 0; j < 8; j++) b8[j] = Bs[kk][tx * 8 + j];
            #pragma unroll
            for (int i = 0; i < 8; i++)
                #pragma unroll
                for (int j = 0; j < 8; j++)
                    acc[i][j] = fmaf(a8[i], b8[j], acc[i][j]);
        }
        __syncthreads();
    }

    const int nbase = n0 + tx * 8;
    if (nbase < N) {   // N % 8 == 0 and tile edge is 64-aligned -> all-or-nothing per thread column group
        #pragma unroll
        for (int i = 0; i < 8; i++) {
            const int m = m0 + ty * 8 + i;
            float4 v0 = make_float4(acc[i][0], acc[i][1], acc[i][2], acc[i][3]);
            float4 v1 = make_float4(acc[i][4], acc[i][5], acc[i][6], acc[i][7]);
            *(float4*)(C + (size_t)m * ldc + nbase)     = v0;
            *(float4*)(C + (size_t)m * ldc + nbase + 4) = v1;
        }
    }
}

// ============================================================================
// delta[t,d] = softplus( sum_{k<64} dbc[t,k] * W_delta[d,k] )
// Block: 128 threads = 128 channels; 8 timesteps per block.
// ============================================================================
__global__ __launch_bounds__(128) void delta_kernel(const float* __restrict__ W_delta)
{
    __shared__ float s_dl[8][64];        // delta_lr rows for 8 timesteps
    __shared__ float s_wT[64][129];      // W_delta transposed (+pad vs bank conflicts)

    const int tid = threadIdx.x;
    const int t0 = blockIdx.x * 8;
    const int d0 = blockIdx.y * 128;

    for (int i = tid; i < 8 * 64; i += 128) {
        int t = i >> 6, k = i & 63;
        s_dl[t][k] = g_dbc[(size_t)(t0 + t) * PROJ + k];
    }
    for (int i = tid; i < 128 * 64; i += 128) {
        int d = i >> 6, k = i & 63;
        s_wT[k][d] = W_delta[(size_t)(d0 + d) * DTR + k];
    }
    __syncthreads();

    float accv[8];
    #pragma unroll
    for (int t = 0; t < 8; t++) accv[t] = 0.f;

    #pragma unroll 8
    for (int k = 0; k < 64; k++) {
        float w = s_wT[k][tid];
        #pragma unroll
        for (int t = 0; t < 8; t++) accv[t] = fmaf(s_dl[t][k], w, accv[t]);
    }

    #pragma unroll
    for (int t = 0; t < 8; t++) {
        float z = accv[t];
        // numerically stable softplus
        float sp = fmaxf(z, 0.f) + log1pf(__expf(-fabsf(z)));
        g_delta[(size_t)(t0 + t) * DI + d0 + tid] = sp;
    }
}

// ============================================================================
// Selective scan. 4 threads per channel, each owns 4 states (float4 loads).
// Block: 128 threads = 32 channels. Grid: 32 blocks.
// h[s] = exp(delta*A[s])*h[s] + delta*x*B[s];  y = sum_s h[s]*C[s] + x*D
// ============================================================================
__global__ __launch_bounds__(128) void scan_kernel(
    const float* __restrict__ x, const float* __restrict__ A_log,
    const float* __restrict__ Dv)
{
    const int tid = threadIdx.x;
    const int d = blockIdx.x * 32 + (tid >> 2);
    const int sg = tid & 3;                     // state group: states 4*sg..4*sg+3

    float a0 = -expf(A_log[d * DS + sg * 4 + 0]);
    float a1 = -expf(A_log[d * DS + sg * 4 + 1]);
    float a2 = -expf(A_log[d * DS + sg * 4 + 2]);
    float a3 = -expf(A_log[d * DS + sg * 4 + 3]);
    const float Dd = Dv[d];

    float h0 = 0.f, h1 = 0.f, h2 = 0.f, h3 = 0.f;

    const float* bbase = g_dbc + DTR + d * DS + sg * 4;
    const float* cbase = bbase + DI * DS;

    // software pipeline depth 1 (prefetch next step)
    float4 B4 = *(const float4*)bbase;
    float4 C4 = *(const float4*)cbase;
    float dt0 = g_delta[d];
    float xt0 = x[d];

    for (int t = 0; t < L_SEQ; t++) {
        float4 nB = B4, nC = C4;
        float ndt = dt0, nxt = xt0;
        const int tn = t + 1;
        if (tn < L_SEQ) {
            nB  = *(const float4*)(bbase + (size_t)tn * PROJ);
            nC  = *(const float4*)(cbase + (size_t)tn * PROJ);
            ndt = g_delta[(size_t)tn * DI + d];
            nxt = x[(size_t)tn * DI + d];
        }

        float dx = dt0 * xt0;
        h0 = fmaf(__expf(dt0 * a0), h0, dx * B4.x);
        h1 = fmaf(__expf(dt0 * a1), h1, dx * B4.y);
        h2 = fmaf(__expf(dt0 * a2), h2, dx * B4.z);
        h3 = fmaf(__expf(dt0 * a3), h3, dx * B4.w);

        float accy = h0 * C4.x + h1 * C4.y + h2 * C4.z + h3 * C4.w;
        accy += __shfl_xor_sync(0xffffffffu, accy, 1);
        accy += __shfl_xor_sync(0xffffffffu, accy, 2);
        if (sg == 0) g_y[(size_t)t * DI + d] = fmaf(xt0, Dd, accy);

        B4 = nB; C4 = nC; dt0 = ndt; xt0 = nxt;
    }
}

// ============================================================================
// Launch
// ============================================================================
extern "C" void kernel_launch(void* const* d_in, const int* in_sizes, int n_in,
                              void* d_out, int out_size)
{
    const float* x       = (const float*)d_in[0];   // (2048, 1024)
    const float* W_in    = (const float*)d_in[1];   // (32832, 1024)
    const float* W_delta = (const float*)d_in[2];   // (1024, 64)
    const float* A_log   = (const float*)d_in[3];   // (1024, 16)
    const float* Dv      = (const float*)d_in[4];   // (1024,)
    const float* W_out   = (const float*)d_in[5];   // (1024, 1024)
    float* out = (float*)d_out;                     // (2048, 1024)

    float *dbc_p, *y_p;
    cudaGetSymbolAddress((void**)&dbc_p, g_dbc);
    cudaGetSymbolAddress((void**)&y_p, g_y);

    // 1) dbc = x @ W_in^T   (M=2048, N=32832, K=1024)
    {
        dim3 grid((PROJ + 127) / 128, L_SEQ / 128);
        sgemm_tn<<<grid, 256>>>(x, W_in, dbc_p, L_SEQ, PROJ, DM, DM, DM, PROJ);
    }
    // 2) delta = softplus(delta_lr @ W_delta^T)
    {
        dim3 grid(L_SEQ / 8, DI / 128);
        delta_kernel<<<grid, 128>>>(W_delta);
    }
    // 3) selective scan -> g_y
    scan_kernel<<<32, 128>>>(x, A_log, Dv);

    // 4) out = y @ W_out^T  (M=2048, N=1024, K=1024)
    {
        dim3 grid(DM / 128, L_SEQ / 128);
        sgemm_tn<<<grid, 256>>>(y_p, W_out, out, L_SEQ, DM, DI, DI, DI, DM);
    }
}

// round 3
// speedup vs baseline: 3.2402x; 3.2402x over previous
#include <cuda_runtime.h>
#include <cuda_bf16.h>
#include <math.h>
#include <stdint.h>

// Problem constants
#define L_SEQ   2048
#define DM      1024
#define DI      1024
#define DTR     64
#define DS      16
#define PROJ    (DTR + 2 * DI * DS)   // 32832
#define NPAD    32896                 // 257 * 128
#define KDIM    1024

// -------- scratch (static device globals; no allocation) --------
__device__ float g_dbc[(size_t)L_SEQ * PROJ];
__device__ float g_delta[(size_t)L_SEQ * DI];
__device__ float g_y[(size_t)L_SEQ * DI];
__device__ __nv_bfloat16 g_xh[(size_t)L_SEQ * DM];
__device__ __nv_bfloat16 g_xl[(size_t)L_SEQ * DM];
__device__ __nv_bfloat16 g_wh[(size_t)NPAD * DM];
__device__ __nv_bfloat16 g_wl[(size_t)NPAD * DM];
__device__ __nv_bfloat16 g_yh[(size_t)L_SEQ * DI];
__device__ __nv_bfloat16 g_yl[(size_t)L_SEQ * DI];
__device__ __nv_bfloat16 g_woh[(size_t)DM * DI];
__device__ __nv_bfloat16 g_wol[(size_t)DM * DI];

// ============================================================================
// helpers
// ============================================================================
__device__ __forceinline__ uint32_t smem_u32(const void* p) {
    uint32_t a;
    asm("{ .reg .u64 t; cvta.to.shared.u64 t, %1; cvt.u32.u64 %0, t; }" : "=r"(a) : "l"(p));
    return a;
}
__device__ __forceinline__ uint32_t swz128(uint32_t o) { return o ^ ((o >> 3) & 0x70); }

__device__ __forceinline__ void cp_async16(uint32_t dst, const void* src) {
    asm volatile("cp.async.cg.shared.global [%0], [%1], 16;" :: "r"(dst), "l"(src));
}
#define CP_COMMIT() asm volatile("cp.async.commit_group;" ::: "memory")
#define CP_WAIT(n)  asm volatile("cp.async.wait_group %0;" :: "n"(n) : "memory")

__device__ __forceinline__ void ldsm4(uint32_t* r, uint32_t addr) {
    asm volatile("ldmatrix.sync.aligned.m8n8.x4.shared.b16 {%0,%1,%2,%3}, [%4];"
        : "=r"(r[0]), "=r"(r[1]), "=r"(r[2]), "=r"(r[3]) : "r"(addr));
}
__device__ __forceinline__ void mma_bf16(float* d, const uint32_t* a, const uint32_t* b) {
    asm volatile(
        "mma.sync.aligned.m16n8k16.row.col.f32.bf16.bf16.f32 "
        "{%0,%1,%2,%3}, {%4,%5,%6,%7}, {%8,%9}, {%0,%1,%2,%3};"
        : "+f"(d[0]), "+f"(d[1]), "+f"(d[2]), "+f"(d[3])
        : "r"(a[0]), "r"(a[1]), "r"(a[2]), "r"(a[3]), "r"(b[0]), "r"(b[1]));
}

// ============================================================================
// Split conversion: hi = bf16(v), lo = bf16(v - hi). Zero-pad beyond n_valid.
// ============================================================================
__global__ __launch_bounds__(256) void split_kernel(
    const float* __restrict__ src, __nv_bfloat16* __restrict__ hi,
    __nv_bfloat16* __restrict__ lo, size_t n_valid, size_t n_total)
{
    size_t i = ((size_t)blockIdx.x * 256 + threadIdx.x) * 4;
    if (i >= n_total) return;
    float4 v = make_float4(0.f, 0.f, 0.f, 0.f);
    if (i < n_valid) v = *(const float4*)(src + i);
    __nv_bfloat16 h0 = __float2bfloat16_rn(v.x);
    __nv_bfloat16 h1 = __float2bfloat16_rn(v.y);
    __nv_bfloat16 h2 = __float2bfloat16_rn(v.z);
    __nv_bfloat16 h3 = __float2bfloat16_rn(v.w);
    __nv_bfloat16 l0 = __float2bfloat16_rn(v.x - __bfloat162float(h0));
    __nv_bfloat16 l1 = __float2bfloat16_rn(v.y - __bfloat162float(h1));
    __nv_bfloat16 l2 = __float2bfloat16_rn(v.z - __bfloat162float(h2));
    __nv_bfloat16 l3 = __float2bfloat16_rn(v.w - __bfloat162float(h3));
    *(__nv_bfloat162*)(hi + i)     = __nv_bfloat162(h0, h1);
    *(__nv_bfloat162*)(hi + i + 2) = __nv_bfloat162(h2, h3);
    *(__nv_bfloat162*)(lo + i)     = __nv_bfloat162(l0, l1);
    *(__nv_bfloat162*)(lo + i + 2) = __nv_bfloat162(l2, l3);
}

// ============================================================================
// Split-bf16 tensor-core GEMM via mma.sync (sm_80+ path, legal on compute_103)
// C[m,n] = A[m,:]·B[n,:] fp32-accurate: AhBh + AlBh + AhBl.
// CTA 128x128, BK=32 bf16, 256 threads (8 warps 2x4, warp tile 64x32),
// double-buffered cp.async, SW128 swizzle, K = 1024.
// ============================================================================
#define GTILE   8192                // one operand tile: 128 rows x 64 B
#define STAGE_B (4 * GTILE)         // Ah, Al, Bh, Bl
#define SMEM_MMA_TOTAL (2 * STAGE_B)
#define NKC     (KDIM / 32)         // 32 k-iters

__global__ __launch_bounds__(256) void gemm_mma(
    const __nv_bfloat16* __restrict__ Ah, const __nv_bfloat16* __restrict__ Al,
    const __nv_bfloat16* __restrict__ Bh, const __nv_bfloat16* __restrict__ Bl,
    float* __restrict__ C, int ldc, int nvalid)
{
    extern __shared__ char smem[];
    const uint32_t sbase = smem_u32(smem);
    const int tid = threadIdx.x;
    const int wid = tid >> 5, lane = tid & 31;
    const int wm = wid & 1, wn = wid >> 1;       // warp grid 2 (m) x 4 (n)

    const int m0 = blockIdx.x * 128;
    const int n0 = blockIdx.y * 128;

    float acc[4][4][4];
    #pragma unroll
    for (int i = 0; i < 4; i++)
        #pragma unroll
        for (int j = 0; j < 4; j++)
            #pragma unroll
            for (int q = 0; q < 4; q++) acc[i][j][q] = 0.f;

    // per-thread load slots: 2 x 16B chunks per tile per stage
    const int q0 = tid * 2;

    auto issue = [&](int kc, int buf) {
        const uint32_t soff = sbase + buf * STAGE_B;
        #pragma unroll
        for (int j = 0; j < 2; j++) {
            const int q = q0 + j;              // 0..511
            const int row = q >> 2, c = q & 3;
            const uint32_t so = swz128((uint32_t)(row * 64 + c * 16));
            const size_t gk = (size_t)kc * 32 + c * 8;
            const size_t ga = (size_t)(m0 + row) * KDIM + gk;
            const size_t gb = (size_t)(n0 + row) * KDIM + gk;
            cp_async16(soff + 0 * GTILE + so, Ah + ga);
            cp_async16(soff + 1 * GTILE + so, Al + ga);
            cp_async16(soff + 2 * GTILE + so, Bh + gb);
            cp_async16(soff + 3 * GTILE + so, Bl + gb);
        }
        CP_COMMIT();
    };

    issue(0, 0);

    #pragma unroll 1
    for (int kc = 0; kc < NKC; kc++) {
        const int buf = kc & 1;
        if (kc + 1 < NKC) { issue(kc + 1, buf ^ 1); CP_WAIT(1); }
        else              { CP_WAIT(0); }
        __syncthreads();

        const uint32_t sA  = sbase + buf * STAGE_B;

        #pragma unroll
        for (int ks = 0; ks < 2; ks++) {
            // ---- B fragments: 2 x ldmatrix.x4 per operand cover nf 0..3 ----
            uint32_t bh[4][2], bl[4][2];
            #pragma unroll
            for (int p = 0; p < 2; p++) {
                const int rowb = wn * 32 + p * 16 + ((lane >> 4) << 3) + (lane & 7);
                const int chb  = ks * 2 + ((lane >> 3) & 1);
                const uint32_t ob = swz128((uint32_t)(rowb * 64 + chb * 16));
                ldsm4(&bh[p * 2][0], sA + 2 * GTILE + ob);
                ldsm4(&bl[p * 2][0], sA + 3 * GTILE + ob);
            }
            // ---- A fragments per mf, then 3 products per nf ----
            #pragma unroll
            for (int mf = 0; mf < 4; mf++) {
                const int rowa = wm * 64 + mf * 16 + (lane & 15);
                const int cha  = ks * 2 + (lane >> 4);
                const uint32_t oa = swz128((uint32_t)(rowa * 64 + cha * 16));
                uint32_t ah[4], al[4];
                ldsm4(ah, sA + 0 * GTILE + oa);
                ldsm4(al, sA + 1 * GTILE + oa);
                #pragma unroll
                for (int nf = 0; nf < 4; nf++) {
                    mma_bf16(acc[mf][nf], ah, bh[nf]);
                    mma_bf16(acc[mf][nf], al, bh[nf]);
                    mma_bf16(acc[mf][nf], ah, bl[nf]);
                }
            }
        }
        __syncthreads();
    }

    // ---- epilogue ----
    const int g = lane >> 2, t4 = lane & 3;
    #pragma unroll
    for (int mf = 0; mf < 4; mf++) {
        #pragma unroll
        for (int nf = 0; nf < 4; nf++) {
            const int m = m0 + wm * 64 + mf * 16 + g;
            const int n = n0 + wn * 32 + nf * 8 + t4 * 2;
            if (n < nvalid) {
                *(float2*)(C + (size_t)m * ldc + n) =
                    make_float2(acc[mf][nf][0], acc[mf][nf][1]);
                *(float2*)(C + (size_t)(m + 8) * ldc + n) =
                    make_float2(acc[mf][nf][2], acc[mf][nf][3]);
            }
        }
    }
}

// ============================================================================
// delta[t,d] = softplus(dbc[t,0:64] · W_delta[d,:])
// ============================================================================
__global__ __launch_bounds__(128) void delta_kernel(const float* __restrict__ W_delta)
{
    __shared__ float s_dl[8][64];
    __shared__ float s_wT[64][129];
    const int tid = threadIdx.x;
    const int t0 = blockIdx.x * 8;
    const int d0 = blockIdx.y * 128;

    for (int i = tid; i < 8 * 64; i += 128) {
        int t = i >> 6, k = i & 63;
        s_dl[t][k] = g_dbc[(size_t)(t0 + t) * PROJ + k];
    }
    for (int i = tid; i < 128 * 64; i += 128) {
        int d = i >> 6, k = i & 63;
        s_wT[k][d] = W_delta[(size_t)(d0 + d) * DTR + k];
    }
    __syncthreads();

    float accv[8];
    #pragma unroll
    for (int t = 0; t < 8; t++) accv[t] = 0.f;
    #pragma unroll 8
    for (int k = 0; k < 64; k++) {
        float w = s_wT[k][tid];
        #pragma unroll
        for (int t = 0; t < 8; t++) accv[t] = fmaf(s_dl[t][k], w, accv[t]);
    }
    #pragma unroll
    for (int t = 0; t < 8; t++) {
        float z = accv[t];
        float sp = fmaxf(z, 0.f) + log1pf(__expf(-fabsf(z)));
        g_delta[(size_t)(t0 + t) * DI + d0 + tid] = sp;
    }
}

// ============================================================================
// Selective scan: 1 thread per (d, s). 128 blocks x 128 threads, prefetch 8.
// ============================================================================
__global__ __launch_bounds__(128) void scan_kernel(
    const float* __restrict__ x, const float* __restrict__ A_log,
    const float* __restrict__ Dv)
{
    const int g = blockIdx.x * 128 + threadIdx.x;    // 0..16383
    const int d = g >> 4, s = g & 15;
    const float a = -expf(A_log[d * DS + s]);
    const float Dd = Dv[d];
    const float* bp = g_dbc + DTR + d * DS + s;
    const float* cp = bp + DI * DS;

    float Bpf[8], Cpf[8], Tpf[8], Xpf[8];
    #pragma unroll
    for (int i = 0; i < 8; i++) {
        Bpf[i] = bp[(size_t)i * PROJ];
        Cpf[i] = cp[(size_t)i * PROJ];
        Tpf[i] = g_delta[(size_t)i * DI + d];
        Xpf[i] = x[(size_t)i * DI + d];
    }
    float h = 0.f;
    #pragma unroll 8
    for (int t = 0; t < L_SEQ; t++) {
        const int sl = t & 7;
        const float dt = Tpf[sl], xt = Xpf[sl], Bv = Bpf[sl], Cv = Cpf[sl];
        const int tn = t + 8;
        if (tn < L_SEQ) {
            Bpf[sl] = bp[(size_t)tn * PROJ];
            Cpf[sl] = cp[(size_t)tn * PROJ];
            Tpf[sl] = g_delta[(size_t)tn * DI + d];
            Xpf[sl] = x[(size_t)tn * DI + d];
        }
        h = fmaf(__expf(dt * a), h, dt * xt * Bv);
        float yv = h * Cv;
        yv += __shfl_xor_sync(0xffffffffu, yv, 1);
        yv += __shfl_xor_sync(0xffffffffu, yv, 2);
        yv += __shfl_xor_sync(0xffffffffu, yv, 4);
        yv += __shfl_xor_sync(0xffffffffu, yv, 8);
        if (s == 0) g_y[(size_t)t * DI + d] = fmaf(xt, Dd, yv);
    }
}

// ============================================================================
// Launch
// ============================================================================
extern "C" void kernel_launch(void* const* d_in, const int* in_sizes, int n_in,
                              void* d_out, int out_size)
{
    const float* x       = (const float*)d_in[0];
    const float* W_in    = (const float*)d_in[1];
    const float* W_delta = (const float*)d_in[2];
    const float* A_log   = (const float*)d_in[3];
    const float* Dv      = (const float*)d_in[4];
    const float* W_out   = (const float*)d_in[5];
    float* out = (float*)d_out;

    float *dbc_p, *y_p;
    __nv_bfloat16 *xh, *xl, *wh, *wl, *yh, *yl, *woh, *wol;
    cudaGetSymbolAddress((void**)&dbc_p, g_dbc);
    cudaGetSymbolAddress((void**)&y_p, g_y);
    cudaGetSymbolAddress((void**)&xh, g_xh);
    cudaGetSymbolAddress((void**)&xl, g_xl);
    cudaGetSymbolAddress((void**)&wh, g_wh);
    cudaGetSymbolAddress((void**)&wl, g_wl);
    cudaGetSymbolAddress((void**)&yh, g_yh);
    cudaGetSymbolAddress((void**)&yl, g_yl);
    cudaGetSymbolAddress((void**)&woh, g_woh);
    cudaGetSymbolAddress((void**)&wol, g_wol);

    cudaFuncSetAttribute(gemm_mma, cudaFuncAttributeMaxDynamicSharedMemorySize,
                         SMEM_MMA_TOTAL);

    // 1) split conversions
    {
        size_t nx = (size_t)L_SEQ * DM;
        split_kernel<<<(unsigned)((nx / 4 + 255) / 256), 256>>>(x, xh, xl, nx, nx);
        size_t nwv = (size_t)PROJ * DM, nwt = (size_t)NPAD * DM;
        split_kernel<<<(unsigned)((nwt / 4 + 255) / 256), 256>>>(W_in, wh, wl, nwv, nwt);
        size_t nwo = (size_t)DM * DI;
        split_kernel<<<(unsigned)((nwo / 4 + 255) / 256), 256>>>(W_out, woh, wol, nwo, nwo);
    }
    // 2) dbc = x @ W_in^T  (tensor cores, split-bf16)
    {
        dim3 grid(L_SEQ / 128, NPAD / 128);   // 16 x 257
        gemm_mma<<<grid, 256, SMEM_MMA_TOTAL>>>(xh, xl, wh, wl, dbc_p, PROJ, PROJ);
    }
    // 3) delta
    {
        dim3 grid(L_SEQ / 8, DI / 128);
        delta_kernel<<<grid, 128>>>(W_delta);
    }
    // 4) scan
    scan_kernel<<<128, 128>>>(x, A_log, Dv);
    // 5) split y, then out = y @ W_out^T (tensor cores)
    {
        size_t ny = (size_t)L_SEQ * DI;
        split_kernel<<<(unsigned)((ny / 4 + 255) / 256), 256>>>(y_p, yh, yl, ny, ny);
        dim3 grid(L_SEQ / 128, DM / 128);     // 16 x 8
        gemm_mma<<<grid, 256, SMEM_MMA_TOTAL>>>(yh, yl, woh, wol, out, DM, DM);
    }
}

// round 4
// speedup vs baseline: 3.3350x; 1.0293x over previous
#include <cuda_runtime.h>
#include <cuda_bf16.h>
#include <math.h>
#include <stdint.h>

// Problem constants
#define L_SEQ   2048
#define DM      1024
#define DI      1024
#define DTR     64
#define DS      16
#define PROJ    (DTR + 2 * DI * DS)   // 32832
#define NPAD    32896                 // 257 * 128
#define KDIM    1024

// -------- scratch (static device globals; no allocation) --------
__device__ float g_dbc[(size_t)L_SEQ * PROJ];
__device__ float g_delta[(size_t)L_SEQ * DI];
__device__ __nv_bfloat16 g_xh[(size_t)L_SEQ * DM];
__device__ __nv_bfloat16 g_xl[(size_t)L_SEQ * DM];
__device__ __nv_bfloat16 g_wh[(size_t)NPAD * DM];
__device__ __nv_bfloat16 g_wl[(size_t)NPAD * DM];
__device__ __nv_bfloat16 g_yh[(size_t)L_SEQ * DI];
__device__ __nv_bfloat16 g_yl[(size_t)L_SEQ * DI];
__device__ __nv_bfloat16 g_woh[(size_t)DM * DI];
__device__ __nv_bfloat16 g_wol[(size_t)DM * DI];

// ============================================================================
// helpers
// ============================================================================
__device__ __forceinline__ uint32_t smem_u32(const void* p) {
    uint32_t a;
    asm("{ .reg .u64 t; cvta.to.shared.u64 t, %1; cvt.u32.u64 %0, t; }" : "=r"(a) : "l"(p));
    return a;
}
__device__ __forceinline__ uint32_t swz128(uint32_t o) { return o ^ ((o >> 3) & 0x70); }

__device__ __forceinline__ void cp_async16(uint32_t dst, const void* src) {
    asm volatile("cp.async.cg.shared.global [%0], [%1], 16;" :: "r"(dst), "l"(src));
}
#define CP_COMMIT() asm volatile("cp.async.commit_group;" ::: "memory")
#define CP_WAIT(n)  asm volatile("cp.async.wait_group %0;" :: "n"(n) : "memory")

__device__ __forceinline__ void ldsm4(uint32_t* r, uint32_t addr) {
    asm volatile("ldmatrix.sync.aligned.m8n8.x4.shared.b16 {%0,%1,%2,%3}, [%4];"
        : "=r"(r[0]), "=r"(r[1]), "=r"(r[2]), "=r"(r[3]) : "r"(addr));
}
__device__ __forceinline__ void mma_bf16(float* d, const uint32_t* a, const uint32_t* b) {
    asm volatile(
        "mma.sync.aligned.m16n8k16.row.col.f32.bf16.bf16.f32 "
        "{%0,%1,%2,%3}, {%4,%5,%6,%7}, {%8,%9}, {%0,%1,%2,%3};"
        : "+f"(d[0]), "+f"(d[1]), "+f"(d[2]), "+f"(d[3])
        : "r"(a[0]), "r"(a[1]), "r"(a[2]), "r"(a[3]), "r"(b[0]), "r"(b[1]));
}

// ============================================================================
// Split conversion: hi = bf16(v), lo = bf16(v - hi). Zero-pad beyond n_valid.
// ============================================================================
__global__ __launch_bounds__(256) void split_kernel(
    const float* __restrict__ src, __nv_bfloat16* __restrict__ hi,
    __nv_bfloat16* __restrict__ lo, size_t n_valid, size_t n_total)
{
    size_t i = ((size_t)blockIdx.x * 256 + threadIdx.x) * 4;
    if (i >= n_total) return;
    float4 v = make_float4(0.f, 0.f, 0.f, 0.f);
    if (i < n_valid) v = *(const float4*)(src + i);
    __nv_bfloat16 h0 = __float2bfloat16_rn(v.x);
    __nv_bfloat16 h1 = __float2bfloat16_rn(v.y);
    __nv_bfloat16 h2 = __float2bfloat16_rn(v.z);
    __nv_bfloat16 h3 = __float2bfloat16_rn(v.w);
    __nv_bfloat16 l0 = __float2bfloat16_rn(v.x - __bfloat162float(h0));
    __nv_bfloat16 l1 = __float2bfloat16_rn(v.y - __bfloat162float(h1));
    __nv_bfloat16 l2 = __float2bfloat16_rn(v.z - __bfloat162float(h2));
    __nv_bfloat16 l3 = __float2bfloat16_rn(v.w - __bfloat162float(h3));
    *(__nv_bfloat162*)(hi + i)     = __nv_bfloat162(h0, h1);
    *(__nv_bfloat162*)(hi + i + 2) = __nv_bfloat162(h2, h3);
    *(__nv_bfloat162*)(lo + i)     = __nv_bfloat162(l0, l1);
    *(__nv_bfloat162*)(lo + i + 2) = __nv_bfloat162(l2, l3);
}

// ============================================================================
// Split-bf16 tensor-core GEMM via mma.sync. 3-stage cp.async pipeline,
// ONE __syncthreads per k-iter, 2-iteration prefetch distance.
// CTA 128x128, BK=32, 256 threads (8 warps 2x4, warp tile 64x32), K=1024.
// ============================================================================
#define GTILE   8192                // one operand tile: 128 rows x 64 B
#define STAGE_B (4 * GTILE)         // Ah, Al, Bh, Bl  (32 KB)
#define NSTAGE  3
#define SMEM_MMA_TOTAL (NSTAGE * STAGE_B)    // 96 KB
#define NKC     (KDIM / 32)         // 32 k-iters

__global__ __launch_bounds__(256, 2) void gemm_mma(
    const __nv_bfloat16* __restrict__ Ah, const __nv_bfloat16* __restrict__ Al,
    const __nv_bfloat16* __restrict__ Bh, const __nv_bfloat16* __restrict__ Bl,
    float* __restrict__ C, int ldc, int nvalid)
{
    extern __shared__ char smem[];
    const uint32_t sbase = smem_u32(smem);
    const int tid = threadIdx.x;
    const int wid = tid >> 5, lane = tid & 31;
    const int wm = wid & 1, wn = wid >> 1;       // warp grid 2 (m) x 4 (n)

    const int m0 = blockIdx.x * 128;
    const int n0 = blockIdx.y * 128;

    float acc[4][4][4];
    #pragma unroll
    for (int i = 0; i < 4; i++)
        #pragma unroll
        for (int j = 0; j < 4; j++)
            #pragma unroll
            for (int q = 0; q < 4; q++) acc[i][j][q] = 0.f;

    const int q0 = tid * 2;

    // issue stage for k-chunk kc into buffer kc % NSTAGE; always commit
    auto issue = [&](int kc) {
        if (kc < NKC) {
            const uint32_t soff = sbase + (kc % NSTAGE) * STAGE_B;
            #pragma unroll
            for (int j = 0; j < 2; j++) {
                const int q = q0 + j;              // 0..511
                const int row = q >> 2, c = q & 3;
                const uint32_t so = swz128((uint32_t)(row * 64 + c * 16));
                const size_t gk = (size_t)kc * 32 + c * 8;
                const size_t ga = (size_t)(m0 + row) * KDIM + gk;
                const size_t gb = (size_t)(n0 + row) * KDIM + gk;
                cp_async16(soff + 0 * GTILE + so, Ah + ga);
                cp_async16(soff + 1 * GTILE + so, Al + ga);
                cp_async16(soff + 2 * GTILE + so, Bh + gb);
                cp_async16(soff + 3 * GTILE + so, Bl + gb);
            }
        }
        CP_COMMIT();
    };

    issue(0);
    issue(1);

    #pragma unroll 1
    for (int kc = 0; kc < NKC; kc++) {
        // group kc must be complete; group kc+1 may remain in flight
        if (kc + 1 < NKC) CP_WAIT(1); else CP_WAIT(0);
        __syncthreads();
        // refill the buffer consumed at iter kc-1 (safe: barrier above)
        issue(kc + 2);

        const uint32_t sA = sbase + (kc % NSTAGE) * STAGE_B;

        #pragma unroll
        for (int ks = 0; ks < 2; ks++) {
            uint32_t bh[4][2], bl[4][2];
            #pragma unroll
            for (int p = 0; p < 2; p++) {
                const int rowb = wn * 32 + p * 16 + ((lane >> 4) << 3) + (lane & 7);
                const int chb  = ks * 2 + ((lane >> 3) & 1);
                const uint32_t ob = swz128((uint32_t)(rowb * 64 + chb * 16));
                ldsm4(&bh[p * 2][0], sA + 2 * GTILE + ob);
                ldsm4(&bl[p * 2][0], sA + 3 * GTILE + ob);
            }
            #pragma unroll
            for (int mf = 0; mf < 4; mf++) {
                const int rowa = wm * 64 + mf * 16 + (lane & 15);
                const int cha  = ks * 2 + (lane >> 4);
                const uint32_t oa = swz128((uint32_t)(rowa * 64 + cha * 16));
                uint32_t ah[4], al[4];
                ldsm4(ah, sA + 0 * GTILE + oa);
                ldsm4(al, sA + 1 * GTILE + oa);
                #pragma unroll
                for (int nf = 0; nf < 4; nf++) {
                    mma_bf16(acc[mf][nf], ah, bh[nf]);
                    mma_bf16(acc[mf][nf], al, bh[nf]);
                    mma_bf16(acc[mf][nf], ah, bl[nf]);
                }
            }
        }
    }

    // ---- epilogue ----
    const int g = lane >> 2, t4 = lane & 3;
    #pragma unroll
    for (int mf = 0; mf < 4; mf++) {
        #pragma unroll
        for (int nf = 0; nf < 4; nf++) {
            const int m = m0 + wm * 64 + mf * 16 + g;
            const int n = n0 + wn * 32 + nf * 8 + t4 * 2;
            if (n < nvalid) {
                *(float2*)(C + (size_t)m * ldc + n) =
                    make_float2(acc[mf][nf][0], acc[mf][nf][1]);
                *(float2*)(C + (size_t)(m + 8) * ldc + n) =
                    make_float2(acc[mf][nf][2], acc[mf][nf][3]);
            }
        }
    }
}

// ============================================================================
// delta[t,d] = softplus(dbc[t,0:64] · W_delta[d,:])
// ============================================================================
__global__ __launch_bounds__(128) void delta_kernel(const float* __restrict__ W_delta)
{
    __shared__ float s_dl[8][64];
    __shared__ float s_wT[64][129];
    const int tid = threadIdx.x;
    const int t0 = blockIdx.x * 8;
    const int d0 = blockIdx.y * 128;

    for (int i = tid; i < 8 * 64; i += 128) {
        int t = i >> 6, k = i & 63;
        s_dl[t][k] = g_dbc[(size_t)(t0 + t) * PROJ + k];
    }
    for (int i = tid; i < 128 * 64; i += 128) {
        int d = i >> 6, k = i & 63;
        s_wT[k][d] = W_delta[(size_t)(d0 + d) * DTR + k];
    }
    __syncthreads();

    float accv[8];
    #pragma unroll
    for (int t = 0; t < 8; t++) accv[t] = 0.f;
    #pragma unroll 8
    for (int k = 0; k < 64; k++) {
        float w = s_wT[k][tid];
        #pragma unroll
        for (int t = 0; t < 8; t++) accv[t] = fmaf(s_dl[t][k], w, accv[t]);
    }
    #pragma unroll
    for (int t = 0; t < 8; t++) {
        float z = accv[t];
        float sp = fmaxf(z, 0.f) + log1pf(__expf(-fabsf(z)));
        g_delta[(size_t)(t0 + t) * DI + d0 + tid] = sp;
    }
}

// ============================================================================
// Selective scan: 1 thread per (d, s). 128 blocks x 128 threads, prefetch 8.
// Writes y directly as split bf16 (yh, yl) for the output GEMM.
// ============================================================================
__global__ __launch_bounds__(128) void scan_kernel(
    const float* __restrict__ x, const float* __restrict__ A_log,
    const float* __restrict__ Dv)
{
    const int g = blockIdx.x * 128 + threadIdx.x;    // 0..16383
    const int d = g >> 4, s = g & 15;
    const float a = -expf(A_log[d * DS + s]);
    const float Dd = Dv[d];
    const float* bp = g_dbc + DTR + d * DS + s;
    const float* cp = bp + DI * DS;

    float Bpf[8], Cpf[8], Tpf[8], Xpf[8];
    #pragma unroll
    for (int i = 0; i < 8; i++) {
        Bpf[i] = bp[(size_t)i * PROJ];
        Cpf[i] = cp[(size_t)i * PROJ];
        Tpf[i] = g_delta[(size_t)i * DI + d];
        Xpf[i] = x[(size_t)i * DI + d];
    }
    float h = 0.f;
    #pragma unroll 8
    for (int t = 0; t < L_SEQ; t++) {
        const int sl = t & 7;
        const float dt = Tpf[sl], xt = Xpf[sl], Bv = Bpf[sl], Cv = Cpf[sl];
        const int tn = t + 8;
        if (tn < L_SEQ) {
            Bpf[sl] = bp[(size_t)tn * PROJ];
            Cpf[sl] = cp[(size_t)tn * PROJ];
            Tpf[sl] = g_delta[(size_t)tn * DI + d];
            Xpf[sl] = x[(size_t)tn * DI + d];
        }
        h = fmaf(__expf(dt * a), h, dt * xt * Bv);
        float yv = h * Cv;
        yv += __shfl_xor_sync(0xffffffffu, yv, 1);
        yv += __shfl_xor_sync(0xffffffffu, yv, 2);
        yv += __shfl_xor_sync(0xffffffffu, yv, 4);
        yv += __shfl_xor_sync(0xffffffffu, yv, 8);
        if (s == 0) {
            float yfull = fmaf(xt, Dd, yv);
            __nv_bfloat16 yh = __float2bfloat16_rn(yfull);
            __nv_bfloat16 yl = __float2bfloat16_rn(yfull - __bfloat162float(yh));
            g_yh[(size_t)t * DI + d] = yh;
            g_yl[(size_t)t * DI + d] = yl;
        }
    }
}

// ============================================================================
// Launch
// ============================================================================
extern "C" void kernel_launch(void* const* d_in, const int* in_sizes, int n_in,
                              void* d_out, int out_size)
{
    const float* x       = (const float*)d_in[0];
    const float* W_in    = (const float*)d_in[1];
    const float* W_delta = (const float*)d_in[2];
    const float* A_log   = (const float*)d_in[3];
    const float* Dv      = (const float*)d_in[4];
    const float* W_out   = (const float*)d_in[5];
    float* out = (float*)d_out;

    float *dbc_p;
    __nv_bfloat16 *xh, *xl, *wh, *wl, *yh, *yl, *woh, *wol;
    cudaGetSymbolAddress((void**)&dbc_p, g_dbc);
    cudaGetSymbolAddress((void**)&xh, g_xh);
    cudaGetSymbolAddress((void**)&xl, g_xl);
    cudaGetSymbolAddress((void**)&wh, g_wh);
    cudaGetSymbolAddress((void**)&wl, g_wl);
    cudaGetSymbolAddress((void**)&yh, g_yh);
    cudaGetSymbolAddress((void**)&yl, g_yl);
    cudaGetSymbolAddress((void**)&woh, g_woh);
    cudaGetSymbolAddress((void**)&wol, g_wol);

    cudaFuncSetAttribute(gemm_mma, cudaFuncAttributeMaxDynamicSharedMemorySize,
                         SMEM_MMA_TOTAL);

    // 1) split conversions
    {
        size_t nx = (size_t)L_SEQ * DM;
        split_kernel<<<(unsigned)((nx / 4 + 255) / 256), 256>>>(x, xh, xl, nx, nx);
        size_t nwv = (size_t)PROJ * DM, nwt = (size_t)NPAD * DM;
        split_kernel<<<(unsigned)((nwt / 4 + 255) / 256), 256>>>(W_in, wh, wl, nwv, nwt);
        size_t nwo = (size_t)DM * DI;
        split_kernel<<<(unsigned)((nwo / 4 + 255) / 256), 256>>>(W_out, woh, wol, nwo, nwo);
    }
    // 2) dbc = x @ W_in^T  (tensor cores, split-bf16)
    {
        dim3 grid(L_SEQ / 128, NPAD / 128);   // 16 x 257
        gemm_mma<<<grid, 256, SMEM_MMA_TOTAL>>>(xh, xl, wh, wl, dbc_p, PROJ, PROJ);
    }
    // 3) delta
    {
        dim3 grid(L_SEQ / 8, DI / 128);
        delta_kernel<<<grid, 128>>>(W_delta);
    }
    // 4) scan (writes split y directly)
    scan_kernel<<<128, 128>>>(x, A_log, Dv);
    // 5) out = y @ W_out^T (tensor cores)
    {
        dim3 grid(L_SEQ / 128, DM / 128);     // 16 x 8
        gemm_mma<<<grid, 256, SMEM_MMA_TOTAL>>>(yh, yl, woh, wol, out, DM, DM);
    }
}

// round 5
// speedup vs baseline: 3.3496x; 1.0044x over previous
#include <cuda_runtime.h>
#include <cuda_bf16.h>
#include <math.h>
#include <stdint.h>

// Problem constants
#define L_SEQ   2048
#define DM      1024
#define DI      1024
#define DTR     64
#define DS      16
#define PROJ    (DTR + 2 * DI * DS)   // 32832
#define NPAD    32896                 // 257 * 128
#define KDIM    1024

// -------- scratch (static device globals; no allocation) --------
__device__ float g_dbc[(size_t)L_SEQ * PROJ];
__device__ float g_delta[(size_t)L_SEQ * DI];
__device__ __nv_bfloat16 g_xh[(size_t)L_SEQ * DM];
__device__ __nv_bfloat16 g_xl[(size_t)L_SEQ * DM];
__device__ __nv_bfloat16 g_wh[(size_t)NPAD * DM];
__device__ __nv_bfloat16 g_wl[(size_t)NPAD * DM];
__device__ __nv_bfloat16 g_yh[(size_t)L_SEQ * DI];
__device__ __nv_bfloat16 g_yl[(size_t)L_SEQ * DI];
__device__ __nv_bfloat16 g_woh[(size_t)DM * DI];
__device__ __nv_bfloat16 g_wol[(size_t)DM * DI];

// ============================================================================
// helpers
// ============================================================================
__device__ __forceinline__ uint32_t smem_u32(const void* p) {
    uint32_t a;
    asm("{ .reg .u64 t; cvta.to.shared.u64 t, %1; cvt.u32.u64 %0, t; }" : "=r"(a) : "l"(p));
    return a;
}
__device__ __forceinline__ uint32_t swz128(uint32_t o) { return o ^ ((o >> 3) & 0x70); }

__device__ __forceinline__ void cp_async16(uint32_t dst, const void* src) {
    asm volatile("cp.async.cg.shared.global [%0], [%1], 16;" :: "r"(dst), "l"(src));
}
#define CP_COMMIT() asm volatile("cp.async.commit_group;" ::: "memory")
#define CP_WAIT(n)  asm volatile("cp.async.wait_group %0;" :: "n"(n) : "memory")

__device__ __forceinline__ void ldsm4(uint32_t* r, uint32_t addr) {
    asm volatile("ldmatrix.sync.aligned.m8n8.x4.shared.b16 {%0,%1,%2,%3}, [%4];"
        : "=r"(r[0]), "=r"(r[1]), "=r"(r[2]), "=r"(r[3]) : "r"(addr));
}
__device__ __forceinline__ void mma_bf16(float* d, const uint32_t* a, const uint32_t* b) {
    asm volatile(
        "mma.sync.aligned.m16n8k16.row.col.f32.bf16.bf16.f32 "
        "{%0,%1,%2,%3}, {%4,%5,%6,%7}, {%8,%9}, {%0,%1,%2,%3};"
        : "+f"(d[0]), "+f"(d[1]), "+f"(d[2]), "+f"(d[3])
        : "r"(a[0]), "r"(a[1]), "r"(a[2]), "r"(a[3]), "r"(b[0]), "r"(b[1]));
}

// ============================================================================
// Split conversion: hi = bf16(v), lo = bf16(v - hi). Zero-pad beyond n_valid.
// ============================================================================
__global__ __launch_bounds__(256) void split_kernel(
    const float* __restrict__ src, __nv_bfloat16* __restrict__ hi,
    __nv_bfloat16* __restrict__ lo, size_t n_valid, size_t n_total)
{
    size_t i = ((size_t)blockIdx.x * 256 + threadIdx.x) * 4;
    if (i >= n_total) return;
    float4 v = make_float4(0.f, 0.f, 0.f, 0.f);
    if (i < n_valid) v = *(const float4*)(src + i);
    __nv_bfloat16 h0 = __float2bfloat16_rn(v.x);
    __nv_bfloat16 h1 = __float2bfloat16_rn(v.y);
    __nv_bfloat16 h2 = __float2bfloat16_rn(v.z);
    __nv_bfloat16 h3 = __float2bfloat16_rn(v.w);
    __nv_bfloat16 l0 = __float2bfloat16_rn(v.x - __bfloat162float(h0));
    __nv_bfloat16 l1 = __float2bfloat16_rn(v.y - __bfloat162float(h1));
    __nv_bfloat16 l2 = __float2bfloat16_rn(v.z - __bfloat162float(h2));
    __nv_bfloat16 l3 = __float2bfloat16_rn(v.w - __bfloat162float(h3));
    *(__nv_bfloat162*)(hi + i)     = __nv_bfloat162(h0, h1);
    *(__nv_bfloat162*)(hi + i + 2) = __nv_bfloat162(h2, h3);
    *(__nv_bfloat162*)(lo + i)     = __nv_bfloat162(l0, l1);
    *(__nv_bfloat162*)(lo + i + 2) = __nv_bfloat162(l2, l3);
}

// ============================================================================
// Split-bf16 tensor-core GEMM via mma.sync. 3-stage cp.async pipeline,
// one __syncthreads per k-iter. MMA issue grouped by PRODUCT so that
// same-accumulator MMAs are 4 issues apart (no RAW stall on acc).
// CTA 128x128, BK=32, 256 threads (8 warps 2x4, warp tile 64x32), K=1024.
// ============================================================================
#define GTILE   8192                // one operand tile: 128 rows x 64 B
#define STAGE_B (4 * GTILE)         // Ah, Al, Bh, Bl  (32 KB)
#define NSTAGE  3
#define SMEM_MMA_TOTAL (NSTAGE * STAGE_B)    // 96 KB
#define NKC     (KDIM / 32)         // 32 k-iters

__global__ __launch_bounds__(256, 2) void gemm_mma(
    const __nv_bfloat16* __restrict__ Ah, const __nv_bfloat16* __restrict__ Al,
    const __nv_bfloat16* __restrict__ Bh, const __nv_bfloat16* __restrict__ Bl,
    float* __restrict__ C, int ldc, int nvalid)
{
    extern __shared__ char smem[];
    const uint32_t sbase = smem_u32(smem);
    const int tid = threadIdx.x;
    const int wid = tid >> 5, lane = tid & 31;
    const int wm = wid & 1, wn = wid >> 1;       // warp grid 2 (m) x 4 (n)

    const int m0 = blockIdx.x * 128;
    const int n0 = blockIdx.y * 128;

    float acc[4][4][4];
    #pragma unroll
    for (int i = 0; i < 4; i++)
        #pragma unroll
        for (int j = 0; j < 4; j++)
            #pragma unroll
            for (int q = 0; q < 4; q++) acc[i][j][q] = 0.f;

    const int q0 = tid * 2;

    auto issue = [&](int kc) {
        if (kc < NKC) {
            const uint32_t soff = sbase + (kc % NSTAGE) * STAGE_B;
            #pragma unroll
            for (int j = 0; j < 2; j++) {
                const int q = q0 + j;              // 0..511
                const int row = q >> 2, c = q & 3;
                const uint32_t so = swz128((uint32_t)(row * 64 + c * 16));
                const size_t gk = (size_t)kc * 32 + c * 8;
                const size_t ga = (size_t)(m0 + row) * KDIM + gk;
                const size_t gb = (size_t)(n0 + row) * KDIM + gk;
                cp_async16(soff + 0 * GTILE + so, Ah + ga);
                cp_async16(soff + 1 * GTILE + so, Al + ga);
                cp_async16(soff + 2 * GTILE + so, Bh + gb);
                cp_async16(soff + 3 * GTILE + so, Bl + gb);
            }
        }
        CP_COMMIT();
    };

    issue(0);
    issue(1);

    #pragma unroll 1
    for (int kc = 0; kc < NKC; kc++) {
        if (kc + 1 < NKC) CP_WAIT(1); else CP_WAIT(0);
        __syncthreads();
        issue(kc + 2);

        const uint32_t sA = sbase + (kc % NSTAGE) * STAGE_B;

        #pragma unroll
        for (int ks = 0; ks < 2; ks++) {
            uint32_t bh[4][2], bl[4][2];
            #pragma unroll
            for (int p = 0; p < 2; p++) {
                const int rowb = wn * 32 + p * 16 + ((lane >> 4) << 3) + (lane & 7);
                const int chb  = ks * 2 + ((lane >> 3) & 1);
                const uint32_t ob = swz128((uint32_t)(rowb * 64 + chb * 16));
                ldsm4(&bh[p * 2][0], sA + 2 * GTILE + ob);
                ldsm4(&bl[p * 2][0], sA + 3 * GTILE + ob);
            }
            #pragma unroll
            for (int mf = 0; mf < 4; mf++) {
                const int rowa = wm * 64 + mf * 16 + (lane & 15);
                const int cha  = ks * 2 + (lane >> 4);
                const uint32_t oa = swz128((uint32_t)(rowa * 64 + cha * 16));
                uint32_t ah[4], al[4];
                ldsm4(ah, sA + 0 * GTILE + oa);
                ldsm4(al, sA + 1 * GTILE + oa);
                // product-grouped issue: same-acc MMAs are 4 apart
                #pragma unroll
                for (int nf = 0; nf < 4; nf++) mma_bf16(acc[mf][nf], ah, bh[nf]);
                #pragma unroll
                for (int nf = 0; nf < 4; nf++) mma_bf16(acc[mf][nf], al, bh[nf]);
                #pragma unroll
                for (int nf = 0; nf < 4; nf++) mma_bf16(acc[mf][nf], ah, bl[nf]);
            }
        }
    }

    // ---- epilogue ----
    const int g = lane >> 2, t4 = lane & 3;
    #pragma unroll
    for (int mf = 0; mf < 4; mf++) {
        #pragma unroll
        for (int nf = 0; nf < 4; nf++) {
            const int m = m0 + wm * 64 + mf * 16 + g;
            const int n = n0 + wn * 32 + nf * 8 + t4 * 2;
            if (n < nvalid) {
                *(float2*)(C + (size_t)m * ldc + n) =
                    make_float2(acc[mf][nf][0], acc[mf][nf][1]);
                *(float2*)(C + (size_t)(m + 8) * ldc + n) =
                    make_float2(acc[mf][nf][2], acc[mf][nf][3]);
            }
        }
    }
}

// ============================================================================
// delta[t,d] = softplus(dbc[t,0:64] · W_delta[d,:])
// ============================================================================
__global__ __launch_bounds__(128) void delta_kernel(const float* __restrict__ W_delta)
{
    __shared__ float s_dl[8][64];
    __shared__ float s_wT[64][129];
    const int tid = threadIdx.x;
    const int t0 = blockIdx.x * 8;
    const int d0 = blockIdx.y * 128;

    for (int i = tid; i < 8 * 64; i += 128) {
        int t = i >> 6, k = i & 63;
        s_dl[t][k] = g_dbc[(size_t)(t0 + t) * PROJ + k];
    }
    for (int i = tid; i < 128 * 64; i += 128) {
        int d = i >> 6, k = i & 63;
        s_wT[k][d] = W_delta[(size_t)(d0 + d) * DTR + k];
    }
    __syncthreads();

    float accv[8];
    #pragma unroll
    for (int t = 0; t < 8; t++) accv[t] = 0.f;
    #pragma unroll 8
    for (int k = 0; k < 64; k++) {
        float w = s_wT[k][tid];
        #pragma unroll
        for (int t = 0; t < 8; t++) accv[t] = fmaf(s_dl[t][k], w, accv[t]);
    }
    #pragma unroll
    for (int t = 0; t < 8; t++) {
        float z = accv[t];
        float sp = fmaxf(z, 0.f) + log1pf(__expf(-fabsf(z)));
        g_delta[(size_t)(t0 + t) * DI + d0 + tid] = sp;
    }
}

// ============================================================================
// Selective scan: 1 thread per (d, s). 128 blocks x 128 threads, prefetch 8.
// Writes y directly as split bf16 (yh, yl) for the output GEMM.
// ============================================================================
__global__ __launch_bounds__(128) void scan_kernel(
    const float* __restrict__ x, const float* __restrict__ A_log,
    const float* __restrict__ Dv)
{
    const int g = blockIdx.x * 128 + threadIdx.x;    // 0..16383
    const int d = g >> 4, s = g & 15;
    const float a = -expf(A_log[d * DS + s]);
    const float Dd = Dv[d];
    const float* bp = g_dbc + DTR + d * DS + s;
    const float* cp = bp + DI * DS;

    float Bpf[8], Cpf[8], Tpf[8], Xpf[8];
    #pragma unroll
    for (int i = 0; i < 8; i++) {
        Bpf[i] = bp[(size_t)i * PROJ];
        Cpf[i] = cp[(size_t)i * PROJ];
        Tpf[i] = g_delta[(size_t)i * DI + d];
        Xpf[i] = x[(size_t)i * DI + d];
    }
    float h = 0.f;
    #pragma unroll 8
    for (int t = 0; t < L_SEQ; t++) {
        const int sl = t & 7;
        const float dt = Tpf[sl], xt = Xpf[sl], Bv = Bpf[sl], Cv = Cpf[sl];
        const int tn = t + 8;
        if (tn < L_SEQ) {
            Bpf[sl] = bp[(size_t)tn * PROJ];
            Cpf[sl] = cp[(size_t)tn * PROJ];
            Tpf[sl] = g_delta[(size_t)tn * DI + d];
            Xpf[sl] = x[(size_t)tn * DI + d];
        }
        h = fmaf(__expf(dt * a), h, dt * xt * Bv);
        float yv = h * Cv;
        yv += __shfl_xor_sync(0xffffffffu, yv, 1);
        yv += __shfl_xor_sync(0xffffffffu, yv, 2);
        yv += __shfl_xor_sync(0xffffffffu, yv, 4);
        yv += __shfl_xor_sync(0xffffffffu, yv, 8);
        if (s == 0) {
            float yfull = fmaf(xt, Dd, yv);
            __nv_bfloat16 yh = __float2bfloat16_rn(yfull);
            __nv_bfloat16 yl = __float2bfloat16_rn(yfull - __bfloat162float(yh));
            g_yh[(size_t)t * DI + d] = yh;
            g_yl[(size_t)t * DI + d] = yl;
        }
    }
}

// ============================================================================
// Launch
// ============================================================================
extern "C" void kernel_launch(void* const* d_in, const int* in_sizes, int n_in,
                              void* d_out, int out_size)
{
    const float* x       = (const float*)d_in[0];
    const float* W_in    = (const float*)d_in[1];
    const float* W_delta = (const float*)d_in[2];
    const float* A_log   = (const float*)d_in[3];
    const float* Dv      = (const float*)d_in[4];
    const float* W_out   = (const float*)d_in[5];
    float* out = (float*)d_out;

    float *dbc_p;
    __nv_bfloat16 *xh, *xl, *wh, *wl, *yh, *yl, *woh, *wol;
    cudaGetSymbolAddress((void**)&dbc_p, g_dbc);
    cudaGetSymbolAddress((void**)&xh, g_xh);
    cudaGetSymbolAddress((void**)&xl, g_xl);
    cudaGetSymbolAddress((void**)&wh, g_wh);
    cudaGetSymbolAddress((void**)&wl, g_wl);
    cudaGetSymbolAddress((void**)&yh, g_yh);
    cudaGetSymbolAddress((void**)&yl, g_yl);
    cudaGetSymbolAddress((void**)&woh, g_woh);
    cudaGetSymbolAddress((void**)&wol, g_wol);

    cudaFuncSetAttribute(gemm_mma, cudaFuncAttributeMaxDynamicSharedMemorySize,
                         SMEM_MMA_TOTAL);

    // 1) split conversions
    {
        size_t nx = (size_t)L_SEQ * DM;
        split_kernel<<<(unsigned)((nx / 4 + 255) / 256), 256>>>(x, xh, xl, nx, nx);
        size_t nwv = (size_t)PROJ * DM, nwt = (size_t)NPAD * DM;
        split_kernel<<<(unsigned)((nwt / 4 + 255) / 256), 256>>>(W_in, wh, wl, nwv, nwt);
        size_t nwo = (size_t)DM * DI;
        split_kernel<<<(unsigned)((nwo / 4 + 255) / 256), 256>>>(W_out, woh, wol, nwo, nwo);
    }
    // 2) dbc = x @ W_in^T  (tensor cores, split-bf16)
    {
        dim3 grid(L_SEQ / 128, NPAD / 128);   // 16 x 257
        gemm_mma<<<grid, 256, SMEM_MMA_TOTAL>>>(xh, xl, wh, wl, dbc_p, PROJ, PROJ);
    }
    // 3) delta
    {
        dim3 grid(L_SEQ / 8, DI / 128);
        delta_kernel<<<grid, 128>>>(W_delta);
    }
    // 4) scan (writes split y directly)
    scan_kernel<<<128, 128>>>(x, A_log, Dv);
    // 5) out = y @ W_out^T (tensor cores)
    {
        dim3 grid(L_SEQ / 128, DM / 128);     // 16 x 8
        gemm_mma<<<grid, 256, SMEM_MMA_TOTAL>>>(yh, yl, woh, wol, out, DM, DM);
    }
}